// round 15
// baseline (speedup 1.0000x reference)
#include <cuda_runtime.h>
#include <cuda_fp16.h>
#include <math.h>
#include <stdint.h>

#define B_SZ 256
#define T_IN 256
#define F_IN 64
#define UE   512
#define UD   256
#define T_OUT 64
#define F_OUT 16

// ---------------------------------------------------------------------------
// Device scratch
// ---------------------------------------------------------------------------
__device__ __half g_hA_e[B_SZ * UE];            // encoder h (UNNORMALIZED, fp16)
__device__ float g_eb_p[4 * UE];                // permuted encoder bias

__device__ __half g_UTe[2048 * 512];            // enc_rec^T fp16 (N permuted)
__device__ __half g_WTe[2048 * 64];             // enc_kernel^T fp16 (N permuted)
__device__ __half g_xA[(size_t)65536 * 64];

__device__ __half g_encA[B_SZ * UE];            // normalized enc h fp16
__device__ __half g_fKT[1024 * 512];
__device__ __half g_bKT[1024 * 512];
__device__ __half g_fUT[1024 * 256];
__device__ __half g_bUT[1024 * 256];
__device__ float g_fb_p[1024];
__device__ float g_bb_p[1024];

__device__ float g_xw_f[B_SZ * 4 * UD];
__device__ float g_xw_b[B_SZ * 4 * UD];
__device__ __half g_hAf[2 * B_SZ * UD];         // double-buffered decoder h
__device__ __half g_hAb[2 * B_SZ * UD];
__device__ float g_dec[(size_t)B_SZ * T_OUT * 2 * UD];

// cross-CTA scalar exchange
__device__ float g_partg[4 * 64 * 32];          // [mt][r][nt] softmax(g) partials
__device__ float g_partc[4 * 64 * 32];          // [mt][r][nt] sum exp(c) partials

// central-counter barriers, one 128B line each:
// enc bar1: 0..3 (mt), enc bar2: 4..7, dec: 8..15
__device__ unsigned g_bar_count[24 * 32];

__device__ __forceinline__ float sigf(float x) {
    return __fdividef(1.f, 1.f + __expf(-x));
}
__device__ __forceinline__ float ftanh(float x) {
    float e = __expf(2.f * x);
    return __fdividef(e - 1.f, e + 1.f);
}
__host__ __device__ __forceinline__ int permN(int n, int nUnits) {
    int gate = n / nUnits, u = n % nUnits;
    return ((u >> 4) << 6) | (gate << 4) | (u & 15);
}

// ---------------------------------------------------------------------------
// mma / ldmatrix helpers
// ---------------------------------------------------------------------------
__device__ __forceinline__ uint32_t smem_u32(const void* p) {
    uint32_t a;
    asm("{ .reg .u64 t; cvta.to.shared.u64 t, %1; cvt.u32.u64 %0, t; }" : "=r"(a) : "l"(p));
    return a;
}
__device__ __forceinline__ uint32_t swz(uint32_t off) { return off ^ ((off >> 3) & 0x70); }

__device__ __forceinline__ void ldsm4(uint32_t* r, uint32_t addr) {
    asm volatile("ldmatrix.sync.aligned.m8n8.x4.shared.b16 {%0,%1,%2,%3}, [%4];"
                 : "=r"(r[0]), "=r"(r[1]), "=r"(r[2]), "=r"(r[3]) : "r"(addr));
}
__device__ __forceinline__ void mma16816(float* c, const uint32_t* a, const uint32_t* b) {
    asm volatile(
        "mma.sync.aligned.m16n8k16.row.col.f32.f16.f16.f32 "
        "{%0,%1,%2,%3}, {%4,%5,%6,%7}, {%8,%9}, {%0,%1,%2,%3};"
        : "+f"(c[0]), "+f"(c[1]), "+f"(c[2]), "+f"(c[3])
        : "r"(a[0]), "r"(a[1]), "r"(a[2]), "r"(a[3]), "r"(b[0]), "r"(b[1]));
}
__device__ __forceinline__ void mma16816h(uint32_t* c, const uint32_t* a, const uint32_t* b) {
    asm volatile(
        "mma.sync.aligned.m16n8k16.row.col.f16.f16.f16.f16 "
        "{%0,%1}, {%2,%3,%4,%5}, {%6,%7}, {%0,%1};"
        : "+r"(c[0]), "+r"(c[1])
        : "r"(a[0]), "r"(a[1]), "r"(a[2]), "r"(a[3]), "r"(b[0]), "r"(b[1]));
}

// central-counter barrier, split arrive/wait (R10 proven)
__device__ __forceinline__ void bar_arrive(int grp) {
    asm volatile("red.release.gpu.global.add.u32 [%0], 1;"
                 :: "l"(g_bar_count + grp * 32) : "memory");
}
__device__ __forceinline__ void bar_wait_sync(int grp, unsigned target) {
    if (threadIdx.x == 0) {
        unsigned v;
        do {
            asm volatile("ld.acquire.gpu.global.u32 %0, [%1];"
                         : "=r"(v) : "l"(g_bar_count + grp * 32) : "memory");
        } while (v < target);
    }
    __syncthreads();
}

extern __shared__ __align__(16) char dynsmem[];

#define ZT_PITCH 68

// ---------------------------------------------------------------------------
// Persistent encoder — R10 structure + early g-partial publication.
// ---------------------------------------------------------------------------
#define ENC_SMEM (18 * 8192 + 64 * ZT_PITCH * 4 + 256)

__global__ void __launch_bounds__(256, 1) enc_persistent() {
    const int tid = threadIdx.x;
    const int lane = tid & 31, wid = tid >> 5;
    const int wm = wid >> 2, wn = wid & 3;
    const int mt = blockIdx.x >> 5;
    const int nt = blockIdx.x & 31;
    const int m0 = mt * 64, n0 = nt * 64;

    char* sB = dynsmem;
    char* sA = dynsmem + 9 * 8192;
    float* zt = (float*)(dynsmem + 18 * 8192);
    float* sInv = (float*)(dynsmem + 18 * 8192 + 64 * ZT_PITCH * 4);
    const uint32_t sbase = smem_u32(dynsmem);
    const uint32_t aSb = sbase + 9 * 8192;

#pragma unroll
    for (int ck = 0; ck < 9; ++ck) {
#pragma unroll
        for (int i = 0; i < 2; ++i) {
            int idx = tid + (i << 8);
            int r = idx >> 3, c8 = (idx & 7) << 3;
            const __half* src = (ck == 0)
                ? g_WTe + (size_t)(n0 + r) * 64 + c8
                : g_UTe + (size_t)(n0 + r) * 512 + ((ck - 1) << 6) + c8;
            *(uint4*)(sB + ck * 8192 + swz((uint32_t)r * 128 + (c8 << 1))) = *(const uint4*)src;
        }
    }

    const int gr = tid >> 2;
    const int ul0 = (tid & 3) << 2;
    float cst[4] = {0.f, 0.f, 0.f, 0.f};

    const uint32_t a_row = (uint32_t)(wm * 32 + (lane & 15)) * 128 + ((lane >> 4) << 4);
    const uint32_t b_row = (uint32_t)(wn * 16 + ((lane >> 4) << 3) + (lane & 7)) * 128
                           + (((lane >> 3) & 1) << 4);

    const int sa_r = tid >> 3;
    const int sa_c8 = (tid & 7) << 3;
    const uint32_t sa_off0 = swz((uint32_t)sa_r * 128 + (sa_c8 << 1));
    const uint32_t sa_off1 = swz((uint32_t)(sa_r + 32) * 128 + (sa_c8 << 1));

    float2 bvr[2];
#pragma unroll
    for (int nf = 0; nf < 2; ++nf)
        bvr[nf] = __ldg((const float2*)(g_eb_p + n0 + wn * 16 + nf * 8 + (lane & 3) * 2));

    // stage x(0)
    {
        uint4 a0 = *(const uint4*)(g_xA + (size_t)(m0 + sa_r) * 64 + sa_c8);
        uint4 a1 = *(const uint4*)(g_xA + (size_t)(m0 + sa_r + 32) * 64 + sa_c8);
        *(uint4*)(sA + sa_off0) = a0;
        *(uint4*)(sA + sa_off1) = a1;
    }
    __syncthreads();

    for (int t = 0; t < 256; ++t) {
        float acc[2][2][4];
        uint32_t hacc[2][2][2];
#pragma unroll
        for (int a = 0; a < 2; ++a)
#pragma unroll
            for (int b = 0; b < 2; ++b) {
#pragma unroll
                for (int q = 0; q < 4; ++q) acc[a][b][q] = 0.f;
                hacc[a][b][0] = 0u; hacc[a][b][1] = 0u;
            }

        // chunk 0 (x·W), fp32 acc — overlaps other CTAs' publication
        {
#pragma unroll
            for (int k16 = 0; k16 < 4; ++k16) {
                const uint32_t kb = (uint32_t)k16 * 32;
                uint32_t af[2][4], bf[4];
                ldsm4(af[0], aSb + swz(a_row + kb));
                ldsm4(af[1], aSb + swz(a_row + 2048 + kb));
                ldsm4(bf, sbase + swz(b_row + kb));
                mma16816(acc[0][0], af[0], bf + 0);
                mma16816(acc[0][1], af[0], bf + 2);
                mma16816(acc[1][0], af[1], bf + 0);
                mma16816(acc[1][1], af[1], bf + 2);
            }
        }

        if (t > 0) {
            bar_wait_sync(4 + mt, 32u * (unsigned)t);   // h(t-1) + S_c partials ready

            const __half* h0 = g_hA_e + (size_t)(m0 + sa_r) * 512;
            const __half* h1 = g_hA_e + (size_t)(m0 + sa_r + 32) * 512;
            uint4 hv[8][2];
#pragma unroll
            for (int ck = 0; ck < 8; ++ck) {
                hv[ck][0] = __ldcg((const uint4*)(h0 + (ck << 6) + sa_c8));
                hv[ck][1] = __ldcg((const uint4*)(h1 + (ck << 6) + sa_c8));
            }
            {
                const float* pc = g_partc + (size_t)(mt * 64 + gr) * 32 + (tid & 3) * 8;
                float ps = 0.f;
#pragma unroll
                for (int j = 0; j < 8; ++j) ps += __ldcg(pc + j);
                ps += __shfl_xor_sync(0xffffffffu, ps, 1);
                ps += __shfl_xor_sync(0xffffffffu, ps, 2);
                if ((tid & 3) == 0) sInv[gr] = __fdividef(1.f, ps);
            }
#pragma unroll
            for (int ck = 0; ck < 8; ++ck) {
                char* dst = sA + (ck + 1) * 8192;
                *(uint4*)(dst + sa_off0) = hv[ck][0];
                *(uint4*)(dst + sa_off1) = hv[ck][1];
            }
            __syncthreads();

#pragma unroll
            for (int c = 1; c < 9; ++c) {
                const uint32_t aS = aSb + (uint32_t)c * 8192;
                const uint32_t bS = sbase + (uint32_t)c * 8192;
#pragma unroll
                for (int k16 = 0; k16 < 4; ++k16) {
                    const uint32_t kb = (uint32_t)k16 * 32;
                    uint32_t af[2][4], bf[4];
                    ldsm4(af[0], aS + swz(a_row + kb));
                    ldsm4(af[1], aS + swz(a_row + 2048 + kb));
                    ldsm4(bf, bS + swz(b_row + kb));
                    mma16816h(hacc[0][0], af[0], bf + 0);
                    mma16816h(hacc[0][1], af[0], bf + 2);
                    mma16816h(hacc[1][0], af[1], bf + 0);
                    mma16816h(hacc[1][1], af[1], bf + 2);
                }
            }
        }

        // ---- epilogue ----
        if (wn == 2) {
            // g-gate columns (32..47): write e_g = exp(z_g) into zt, reduce,
            // publish partials, and arrive bar1 EARLY (only these 64 threads
            // produce the data bar1 certifies).
            float prow[2][2] = {{0.f, 0.f}, {0.f, 0.f}};
#pragma unroll
            for (int mf = 0; mf < 2; ++mf) {
                const int row_l = wm * 32 + mf * 16 + (lane >> 2);
                float sc0 = (t > 0) ? sInv[row_l] : 0.f;
                float sc1 = (t > 0) ? sInv[row_l + 8] : 0.f;
#pragma unroll
                for (int nf = 0; nf < 2; ++nf) {
                    const int col = 32 + nf * 8 + (lane & 3) * 2;
                    float2 f0 = __half22float2(*(const __half2*)&hacc[mf][nf][0]);
                    float2 f1 = __half22float2(*(const __half2*)&hacc[mf][nf][1]);
                    float e0 = __expf(acc[mf][nf][0] + bvr[nf].x + sc0 * f0.x);
                    float e1 = __expf(acc[mf][nf][1] + bvr[nf].y + sc0 * f0.y);
                    float e2 = __expf(acc[mf][nf][2] + bvr[nf].x + sc1 * f1.x);
                    float e3 = __expf(acc[mf][nf][3] + bvr[nf].y + sc1 * f1.y);
                    zt[row_l * ZT_PITCH + col] = e0;
                    zt[row_l * ZT_PITCH + col + 1] = e1;
                    zt[(row_l + 8) * ZT_PITCH + col] = e2;
                    zt[(row_l + 8) * ZT_PITCH + col + 1] = e3;
                    prow[mf][0] += e0 + e1;
                    prow[mf][1] += e2 + e3;
                }
            }
#pragma unroll
            for (int mf = 0; mf < 2; ++mf)
#pragma unroll
                for (int hh = 0; hh < 2; ++hh) {
                    prow[mf][hh] += __shfl_xor_sync(0xffffffffu, prow[mf][hh], 1);
                    prow[mf][hh] += __shfl_xor_sync(0xffffffffu, prow[mf][hh], 2);
                }
            if ((lane & 3) == 0) {
                const int rbase = wm * 32 + (lane >> 2);
#pragma unroll
                for (int mf = 0; mf < 2; ++mf) {
                    g_partg[(size_t)(mt * 64 + rbase + mf * 16) * 32 + nt] = prow[mf][0];
                    g_partg[(size_t)(mt * 64 + rbase + mf * 16 + 8) * 32 + nt] = prow[mf][1];
                }
            }
            asm volatile("bar.sync 1, 64;" ::: "memory");   // both g-warps done
            if (wid == 2 && lane == 0) bar_arrive(mt);
        } else {
            // i/f/o columns: raw z into zt
#pragma unroll
            for (int mf = 0; mf < 2; ++mf) {
                const int row_l = wm * 32 + mf * 16 + (lane >> 2);
                float sc0 = (t > 0) ? sInv[row_l] : 0.f;
                float sc1 = (t > 0) ? sInv[row_l + 8] : 0.f;
#pragma unroll
                for (int nf = 0; nf < 2; ++nf) {
                    const int col = wn * 16 + nf * 8 + (lane & 3) * 2;
                    float2 f0 = __half22float2(*(const __half2*)&hacc[mf][nf][0]);
                    float2 f1 = __half22float2(*(const __half2*)&hacc[mf][nf][1]);
                    zt[row_l * ZT_PITCH + col]     = acc[mf][nf][0] + bvr[nf].x + sc0 * f0.x;
                    zt[row_l * ZT_PITCH + col + 1] = acc[mf][nf][1] + bvr[nf].y + sc0 * f0.y;
                    zt[(row_l + 8) * ZT_PITCH + col]     = acc[mf][nf][2] + bvr[nf].x + sc1 * f1.x;
                    zt[(row_l + 8) * ZT_PITCH + col + 1] = acc[mf][nf][3] + bvr[nf].y + sc1 * f1.y;
                }
            }
        }
        __syncthreads();

        // stage x(t+1) while other CTAs finish publishing g partials
        if (t + 1 < 256) {
            const __half* xb = g_xA + ((size_t)(t + 1) * 256 + m0) * 64;
            uint4 a0 = *(const uint4*)(xb + (size_t)sa_r * 64 + sa_c8);
            uint4 a1 = *(const uint4*)(xb + (size_t)(sa_r + 32) * 64 + sa_c8);
            *(uint4*)(sA + sa_off0) = a0;
            *(uint4*)(sA + sa_off1) = a1;
        }

        bar_wait_sync(mt, 32u * (unsigned)(t + 1));

        // gates: S_g, then local c/h update (e_g read pre-exp'd from zt)
        {
            const float* pg = g_partg + (size_t)(mt * 64 + gr) * 32 + (tid & 3) * 8;
            float q = 0.f;
#pragma unroll
            for (int j = 0; j < 8; ++j) q += __ldcg(pg + j);
            q += __shfl_xor_sync(0xffffffffu, q, 1);
            q += __shfl_xor_sync(0xffffffffu, q, 2);
            float invsg = __fdividef(1.f, q);

            float4 zi4 = *(float4*)(zt + gr * ZT_PITCH + 0 + ul0);
            float4 zf4 = *(float4*)(zt + gr * ZT_PITCH + 16 + ul0);
            float4 eg4 = *(float4*)(zt + gr * ZT_PITCH + 32 + ul0);   // already exp'd
            float4 zo4 = *(float4*)(zt + gr * ZT_PITCH + 48 + ul0);
            float zi[4] = {zi4.x, zi4.y, zi4.z, zi4.w};
            float zf[4] = {zf4.x, zf4.y, zf4.z, zf4.w};
            float eg[4] = {eg4.x, eg4.y, eg4.z, eg4.w};
            float zo[4] = {zo4.x, zo4.y, zo4.z, zo4.w};

            float hun[4], pc = 0.f;
#pragma unroll
            for (int k = 0; k < 4; ++k) {
                float cn = sigf(zf[k]) * cst[k] + sigf(zi[k]) * (eg[k] * invsg);
                cst[k] = cn;
                float ec = __expf(cn);
                pc += ec;
                hun[k] = sigf(zo[k]) * ec;
            }
            pc += __shfl_xor_sync(0xffffffffu, pc, 1);
            pc += __shfl_xor_sync(0xffffffffu, pc, 2);
            if ((tid & 3) == 0) g_partc[(size_t)(mt * 64 + gr) * 32 + nt] = pc;

            __half* hp = g_hA_e + (size_t)(m0 + gr) * 512 + 16 * nt + ul0;
            *(__half2*)hp = __floats2half2_rn(hun[0], hun[1]);
            *(__half2*)(hp + 2) = __floats2half2_rn(hun[2], hun[3]);
        }
        __syncthreads();
        if (tid == 0) bar_arrive(4 + mt);
    }
}

// normalize final encoder h into g_encA using S_c partials
__global__ void __launch_bounds__(256) prep_encA_norm() {
    const int b = blockIdx.x;
    const int mt = b >> 6, r = b & 63;
    __shared__ float s;
    if (threadIdx.x < 32) {
        float v = g_partc[(size_t)(mt * 64 + r) * 32 + threadIdx.x];
#pragma unroll
        for (int o = 16; o; o >>= 1) v += __shfl_xor_sync(0xffffffffu, v, o);
        if (threadIdx.x == 0) s = v;
    }
    __syncthreads();
    float inv = __fdividef(1.f, s);
    for (int j = threadIdx.x; j < 512; j += 256)
        g_encA[(size_t)b * 512 + j] =
            __float2half_rn(__half2float(g_hA_e[(size_t)b * 512 + j]) * inv);
}

// ---------------------------------------------------------------------------
// Persistent decoder — R10 structure; g_dec store moved off the critical path.
// ---------------------------------------------------------------------------
#define DEC_SMEM (8 * 8192 + 64 * ZT_PITCH * 4)

__global__ void __launch_bounds__(256, 1) dec_persistent() {
    const int tid = threadIdx.x;
    const int lane = tid & 31, wid = tid >> 5;
    const int wm = wid >> 2, wn = wid & 3;
    const int dir = blockIdx.x >> 6;
    const int g = (blockIdx.x >> 4) & 3;
    const int nt = blockIdx.x & 15;
    const int m0 = g * 64, n0 = nt * 64;
    const int bid = 8 + dir * 4 + g;

    const __half* Bw = dir ? g_bUT : g_fUT;
    __half* Ah = dir ? g_hAb : g_hAf;
    const float* xw = dir ? g_xw_b : g_xw_f;

    char* sB = dynsmem;
    char* sA = dynsmem + 4 * 8192;
    float* zt = (float*)(dynsmem + 8 * 8192);
    const uint32_t sbase = smem_u32(dynsmem);
    const uint32_t aSb = sbase + 4 * 8192;

    const int sa_r = tid >> 3;
    const int sa_c8 = (tid & 7) << 3;
    const uint32_t sa_off0 = swz((uint32_t)sa_r * 128 + (sa_c8 << 1));
    const uint32_t sa_off1 = swz((uint32_t)(sa_r + 32) * 128 + (sa_c8 << 1));

#pragma unroll
    for (int ck = 0; ck < 4; ++ck) {
        *(uint4*)(sB + ck * 8192 + sa_off0) =
            *(const uint4*)(Bw + (size_t)(n0 + sa_r) * 256 + (ck << 6) + sa_c8);
        *(uint4*)(sB + ck * 8192 + sa_off1) =
            *(const uint4*)(Bw + (size_t)(n0 + sa_r + 32) * 256 + (ck << 6) + sa_c8);
    }

    const int gr = tid >> 2;
    const int ul0 = (tid & 3) << 2;
    const int grow = m0 + gr;
    float cst[4] = {0.f, 0.f, 0.f, 0.f};

    const uint32_t a_row = (uint32_t)(wm * 32 + (lane & 15)) * 128 + ((lane >> 4) << 4);
    const uint32_t b_row = (uint32_t)(wn * 16 + ((lane >> 4) << 3) + (lane & 7)) * 128
                           + (((lane >> 3) & 1) << 4);

    float2 xwr[2][2][2];
#pragma unroll
    for (int mf = 0; mf < 2; ++mf) {
        const int row0 = m0 + wm * 32 + mf * 16 + (lane >> 2);
#pragma unroll
        for (int nf = 0; nf < 2; ++nf) {
            const int col = n0 + wn * 16 + nf * 8 + (lane & 3) * 2;
            xwr[mf][nf][0] = __ldg((const float2*)(xw + (size_t)row0 * 1024 + col));
            xwr[mf][nf][1] = __ldg((const float2*)(xw + (size_t)(row0 + 8) * 1024 + col));
        }
    }
    __syncthreads();

    for (int s = 0; s < 64; ++s) {
        uint32_t hacc[2][2][2];
#pragma unroll
        for (int a = 0; a < 2; ++a)
#pragma unroll
            for (int b = 0; b < 2; ++b) { hacc[a][b][0] = 0u; hacc[a][b][1] = 0u; }

        if (s > 0) {
            bar_wait_sync(bid, 16u * (unsigned)s);
            const __half* hsrc = Ah + (size_t)((s - 1) & 1) * (B_SZ * UD);
            const __half* h0 = hsrc + (size_t)(m0 + sa_r) * 256;
            const __half* h1 = hsrc + (size_t)(m0 + sa_r + 32) * 256;
            uint4 hv[4][2];
#pragma unroll
            for (int ck = 0; ck < 4; ++ck) {
                hv[ck][0] = __ldcg((const uint4*)(h0 + (ck << 6) + sa_c8));
                hv[ck][1] = __ldcg((const uint4*)(h1 + (ck << 6) + sa_c8));
            }
#pragma unroll
            for (int ck = 0; ck < 4; ++ck) {
                char* dst = sA + ck * 8192;
                *(uint4*)(dst + sa_off0) = hv[ck][0];
                *(uint4*)(dst + sa_off1) = hv[ck][1];
            }
            __syncthreads();
#pragma unroll
            for (int c = 0; c < 4; ++c) {
                const uint32_t aS = aSb + (uint32_t)c * 8192;
                const uint32_t bS = sbase + (uint32_t)c * 8192;
#pragma unroll
                for (int k16 = 0; k16 < 4; ++k16) {
                    const uint32_t kb = (uint32_t)k16 * 32;
                    uint32_t af[2][4], bf[4];
                    ldsm4(af[0], aS + swz(a_row + kb));
                    ldsm4(af[1], aS + swz(a_row + 2048 + kb));
                    ldsm4(bf, bS + swz(b_row + kb));
                    mma16816h(hacc[0][0], af[0], bf + 0);
                    mma16816h(hacc[0][1], af[0], bf + 2);
                    mma16816h(hacc[1][0], af[1], bf + 0);
                    mma16816h(hacc[1][1], af[1], bf + 2);
                }
            }
        }

#pragma unroll
        for (int mf = 0; mf < 2; ++mf) {
            const int row_l = wm * 32 + mf * 16 + (lane >> 2);
#pragma unroll
            for (int nf = 0; nf < 2; ++nf) {
                const int col = wn * 16 + nf * 8 + (lane & 3) * 2;
                float2 f0 = __half22float2(*(const __half2*)&hacc[mf][nf][0]);
                float2 f1 = __half22float2(*(const __half2*)&hacc[mf][nf][1]);
                if (s == 0) { f0.x = f0.y = f1.x = f1.y = 0.f; }
                zt[row_l * ZT_PITCH + col]     = xwr[mf][nf][0].x + f0.x;
                zt[row_l * ZT_PITCH + col + 1] = xwr[mf][nf][0].y + f0.y;
                zt[(row_l + 8) * ZT_PITCH + col]     = xwr[mf][nf][1].x + f1.x;
                zt[(row_l + 8) * ZT_PITCH + col + 1] = xwr[mf][nf][1].y + f1.y;
            }
        }
        __syncthreads();

        float hn[4];
        {
            float4 zi4 = *(float4*)(zt + gr * ZT_PITCH + 0 + ul0);
            float4 zf4 = *(float4*)(zt + gr * ZT_PITCH + 16 + ul0);
            float4 zg4 = *(float4*)(zt + gr * ZT_PITCH + 32 + ul0);
            float4 zo4 = *(float4*)(zt + gr * ZT_PITCH + 48 + ul0);
            float zi[4] = {zi4.x, zi4.y, zi4.z, zi4.w};
            float zf[4] = {zf4.x, zf4.y, zf4.z, zf4.w};
            float zg[4] = {zg4.x, zg4.y, zg4.z, zg4.w};
            float zo[4] = {zo4.x, zo4.y, zo4.z, zo4.w};

#pragma unroll
            for (int k = 0; k < 4; ++k) {
                float cn = sigf(zf[k]) * cst[k] + sigf(zi[k]) * ftanh(zg[k]);
                cst[k] = cn;
                hn[k] = sigf(zo[k]) * ftanh(cn);
            }

            // publish h first (inter-CTA critical path)
            __half* hp = Ah + (size_t)(s & 1) * (B_SZ * UD)
                         + (size_t)grow * 256 + 16 * nt + ul0;
            *(__half2*)hp = __floats2half2_rn(hn[0], hn[1]);
            *(__half2*)(hp + 2) = __floats2half2_rn(hn[2], hn[3]);
        }
        __syncthreads();
        if (tid == 0) bar_arrive(bid);

        // g_dec store off the critical path (consumed only after kernel end)
        {
            int tpos = dir ? (T_OUT - 1 - s) : s;
            float* dp = g_dec + ((size_t)grow * T_OUT + tpos) * 512 + dir * 256 + 16 * nt + ul0;
            *(float4*)dp = make_float4(hn[0], hn[1], hn[2], hn[3]);
        }
    }
}

// ---------------------------------------------------------------------------
// Generic fp16 TC GEMM (decoder input projection)
// ---------------------------------------------------------------------------
#define STAGE_BYTES 24576
#define GEMM_SMEM (2 * STAGE_BYTES + 1024)

__global__ void __launch_bounds__(256) gemm_tc(
    const __half* __restrict__ A0, const __half* __restrict__ A1, int lda,
    const __half* __restrict__ B0, const __half* __restrict__ B1, int ldb,
    int K,
    const float* __restrict__ bias0, const float* __restrict__ bias1,
    float* __restrict__ C0, float* __restrict__ C1, int ldc)
{
    const int dir = blockIdx.z;
    const __half* A = dir ? A1 : A0;
    const __half* B = dir ? B1 : B0;
    const float* bias = dir ? bias1 : bias0;
    float* C = dir ? C1 : C0;

    const int n0 = blockIdx.x * 128;
    const int m0 = blockIdx.y * 64;
    const int tid = threadIdx.x;
    const int lane = tid & 31;
    const int wid = tid >> 5;
    const int wm = wid >> 2;
    const int wn = wid & 3;

    const uint32_t raw = smem_u32(dynsmem);
    const uint32_t sbase = (raw + 1023) & ~1023u;
    char* sb = dynsmem + (sbase - raw);

    float acc[2][4][4];
#pragma unroll
    for (int i = 0; i < 2; ++i)
#pragma unroll
        for (int j = 0; j < 4; ++j)
#pragma unroll
            for (int k = 0; k < 4; ++k) acc[i][j][k] = 0.f;

    const __half* Abase = A + (size_t)m0 * lda;
    const __half* Bbase = B + (size_t)n0 * ldb;

    uint4 rA[2], rB[4];
    const int NC = K >> 6;

#define LOAD_CHUNK(cc) do { int k0 = (cc) << 6;                                   \
    _Pragma("unroll") for (int i = 0; i < 2; ++i) {                               \
        int idx = tid + (i << 8); int r = idx >> 3; int c8 = (idx & 7) << 3;      \
        rA[i] = *(const uint4*)(Abase + (size_t)r * lda + k0 + c8); }             \
    _Pragma("unroll") for (int i = 0; i < 4; ++i) {                               \
        int idx = tid + (i << 8); int r = idx >> 3; int c8 = (idx & 7) << 3;      \
        rB[i] = *(const uint4*)(Bbase + (size_t)r * ldb + k0 + c8); } } while (0)

#define STORE_CHUNK(s) do { char* sA = sb + (s) * STAGE_BYTES; char* sB = sA + 8192; \
    _Pragma("unroll") for (int i = 0; i < 2; ++i) {                                  \
        int idx = tid + (i << 8); int r = idx >> 3; int c8 = (idx & 7) << 3;         \
        *(uint4*)(sA + swz((uint32_t)r * 128 + (c8 << 1))) = rA[i]; }                \
    _Pragma("unroll") for (int i = 0; i < 4; ++i) {                                  \
        int idx = tid + (i << 8); int r = idx >> 3; int c8 = (idx & 7) << 3;         \
        *(uint4*)(sB + swz((uint32_t)r * 128 + (c8 << 1))) = rB[i]; } } while (0)

    LOAD_CHUNK(0);
    STORE_CHUNK(0);

    for (int c = 0; c < NC; ++c) {
        __syncthreads();
        if (c + 1 < NC) LOAD_CHUNK(c + 1);

        const uint32_t aS = sbase + (c & 1) * STAGE_BYTES;
        const uint32_t bS = aS + 8192;
        const uint32_t a_row = (uint32_t)(wm * 32 + (lane & 15)) * 128 + ((lane >> 4) << 4);
        const uint32_t b_row = (uint32_t)(wn * 32 + ((lane >> 4) << 3) + (lane & 7)) * 128
                               + (((lane >> 3) & 1) << 4);
#pragma unroll
        for (int k16 = 0; k16 < 4; ++k16) {
            const uint32_t kb = (uint32_t)k16 * 32;
            uint32_t af[2][4], bf[2][4];
#pragma unroll
            for (int mf = 0; mf < 2; ++mf)
                ldsm4(af[mf], aS + swz(a_row + (uint32_t)mf * 16 * 128 + kb));
#pragma unroll
            for (int nh = 0; nh < 2; ++nh)
                ldsm4(bf[nh], bS + swz(b_row + (uint32_t)nh * 16 * 128 + kb));
#pragma unroll
            for (int mf = 0; mf < 2; ++mf)
#pragma unroll
                for (int nf = 0; nf < 4; ++nf)
                    mma16816(acc[mf][nf], af[mf], &bf[nf >> 1][(nf & 1) * 2]);
        }

        if (c + 1 < NC) STORE_CHUNK((c + 1) & 1);
    }

#pragma unroll
    for (int mf = 0; mf < 2; ++mf) {
        const int row0 = m0 + wm * 32 + mf * 16 + (lane >> 2);
#pragma unroll
        for (int nf = 0; nf < 4; ++nf) {
            const int col = n0 + wn * 32 + nf * 8 + (lane & 3) * 2;
            float2 bv = *(const float2*)(bias + col);
            *(float2*)(C + (size_t)row0 * ldc + col) =
                make_float2(acc[mf][nf][0] + bv.x, acc[mf][nf][1] + bv.y);
            *(float2*)(C + (size_t)(row0 + 8) * ldc + col) =
                make_float2(acc[mf][nf][2] + bv.x, acc[mf][nf][3] + bv.y);
        }
    }
#undef LOAD_CHUNK
#undef STORE_CHUNK
}

// ---------------------------------------------------------------------------
// Prep kernels (consolidated)
// ---------------------------------------------------------------------------
__global__ void __launch_bounds__(256) prep_all(
    const float* __restrict__ x, const float* __restrict__ eb,
    const float* __restrict__ fb, const float* __restrict__ bb)
{
    const int total = 65536 * 64;
    int gi = blockIdx.x * blockDim.x + threadIdx.x;
    if (gi < 24 * 32) g_bar_count[gi] = 0u;
    if (gi < 2048) g_eb_p[permN(gi, 512)] = eb[gi];
    if (gi >= 2048 && gi < 3072) {
        int n = gi - 2048;
        int np = permN(n, 256);
        g_fb_p[np] = fb[n];
        g_bb_p[np] = bb[n];
    }
    for (int i = gi; i < total; i += gridDim.x * blockDim.x) {
        int r = i >> 6, c = i & 63;
        int t = r >> 8, b = r & 255;
        g_xA[(size_t)r * 64 + c] = __float2half_rn(x[((size_t)b * T_IN + t) * F_IN + c]);
    }
}

// One launch for all 6 weight transposes. blockIdx.z selects the matrix.
__global__ void __launch_bounds__(256) transpose_all(
    const float* __restrict__ eU, const float* __restrict__ eW,
    const float* __restrict__ fK, const float* __restrict__ bK,
    const float* __restrict__ fU, const float* __restrict__ bU,
    __half* __restrict__ UTe, __half* __restrict__ WTe,
    __half* __restrict__ fKT, __half* __restrict__ bKT,
    __half* __restrict__ fUT, __half* __restrict__ bUT)
{
    const float* in; __half* out;
    int K, N, nUnits;
    switch (blockIdx.z) {
        case 0: in = eU; out = UTe; K = 512; N = 2048; nUnits = 512; break;
        case 1: in = eW; out = WTe; K = 64;  N = 2048; nUnits = 512; break;
        case 2: in = fK; out = fKT; K = 512; N = 1024; nUnits = 256; break;
        case 3: in = bK; out = bKT; K = 512; N = 1024; nUnits = 256; break;
        case 4: in = fU; out = fUT; K = 256; N = 1024; nUnits = 256; break;
        default: in = bU; out = bUT; K = 256; N = 1024; nUnits = 256; break;
    }
    const int nb = blockIdx.x * 32;
    const int kb = blockIdx.y * 32;
    if (nb >= N || kb >= K) return;

    __shared__ float tile[32][33];
    const int tx = threadIdx.x & 31;
    const int ty = threadIdx.x >> 5;
#pragma unroll
    for (int i = ty; i < 32; i += 8)
        tile[i][tx] = in[(size_t)(kb + i) * N + nb + tx];
    __syncthreads();
#pragma unroll
    for (int i = ty; i < 32; i += 8) {
        int n = nb + i;
        int np = permN(n, nUnits);
        out[(size_t)np * K + kb + tx] = __float2half_rn(tile[tx][i]);
    }
}

__global__ void __launch_bounds__(256) dense_kernel_(
    const float* __restrict__ Wd, const float* __restrict__ bd, float* __restrict__ out)
{
    __shared__ float sdec[16][512];
    const int row0 = blockIdx.x * 16;
#pragma unroll
    for (int i = 0; i < 8; ++i) {
        int f = threadIdx.x + i * 256;
        int r = f >> 7;
        int k4 = (f & 127) * 4;
        *reinterpret_cast<float4*>(&sdec[r][k4]) =
            *reinterpret_cast<const float4*>(g_dec + (size_t)(row0 + r) * 512 + k4);
    }
    __syncthreads();
    const int r = threadIdx.x >> 4;
    const int m = threadIdx.x & 15;
    float acc = 0.f;
#pragma unroll 8
    for (int k = 0; k < 512; ++k)
        acc += sdec[r][k] * __ldg(Wd + k * 16 + m);
    out[(size_t)(row0 + r) * 16 + m] = acc + bd[m];
}

// ---------------------------------------------------------------------------
// Launch — 7 launches total
// ---------------------------------------------------------------------------
extern "C" void kernel_launch(void* const* d_in, const int* in_sizes, int n_in,
                              void* d_out, int out_size) {
    const float* x   = (const float*)d_in[0];
    const float* eW  = (const float*)d_in[1];
    const float* eU  = (const float*)d_in[2];
    const float* eb  = (const float*)d_in[3];
    const float* fK  = (const float*)d_in[4];
    const float* fU  = (const float*)d_in[5];
    const float* fb  = (const float*)d_in[6];
    const float* bK  = (const float*)d_in[7];
    const float* bU  = (const float*)d_in[8];
    const float* bb  = (const float*)d_in[9];
    const float* dW  = (const float*)d_in[10];
    const float* db  = (const float*)d_in[11];
    float* out = (float*)d_out;

    cudaFuncSetAttribute(gemm_tc, cudaFuncAttributeMaxDynamicSharedMemorySize, GEMM_SMEM);
    cudaFuncSetAttribute(enc_persistent, cudaFuncAttributeMaxDynamicSharedMemorySize, ENC_SMEM);
    cudaFuncSetAttribute(dec_persistent, cudaFuncAttributeMaxDynamicSharedMemorySize, DEC_SMEM);

    float *xwf_p, *xwb_p, *fbp_p, *bbp_p;
    __half *UTe_p, *WTe_p, *encA_p, *fKT_p, *bKT_p, *fUT_p, *bUT_p;
    cudaGetSymbolAddress((void**)&xwf_p, g_xw_f);
    cudaGetSymbolAddress((void**)&xwb_p, g_xw_b);
    cudaGetSymbolAddress((void**)&fbp_p, g_fb_p);
    cudaGetSymbolAddress((void**)&bbp_p, g_bb_p);
    cudaGetSymbolAddress((void**)&UTe_p, g_UTe);
    cudaGetSymbolAddress((void**)&WTe_p, g_WTe);
    cudaGetSymbolAddress((void**)&encA_p, g_encA);
    cudaGetSymbolAddress((void**)&fKT_p, g_fKT);
    cudaGetSymbolAddress((void**)&bKT_p, g_bKT);
    cudaGetSymbolAddress((void**)&fUT_p, g_fUT);
    cudaGetSymbolAddress((void**)&bUT_p, g_bUT);

    prep_all<<<1024, 256>>>(x, eb, fb, bb);
    transpose_all<<<dim3(64, 16, 6), 256>>>(eU, eW, fK, bK, fU, bU,
                                            UTe_p, WTe_p, fKT_p, bKT_p, fUT_p, bUT_p);

    enc_persistent<<<128, 256, ENC_SMEM>>>();

    prep_encA_norm<<<B_SZ, 256>>>();
    gemm_tc<<<dim3(8, 4, 2), 256, GEMM_SMEM>>>(
        encA_p, encA_p, 512, fKT_p, bKT_p, 512, 512,
        fbp_p, bbp_p, xwf_p, xwb_p, 1024);

    dec_persistent<<<128, 256, DEC_SMEM>>>();

    dense_kernel_<<<(B_SZ * T_OUT) / 16, 256>>>(dW, db, out);
}

// round 16
// speedup vs baseline: 1.0086x; 1.0086x over previous
#include <cuda_runtime.h>
#include <cuda_fp16.h>
#include <math.h>
#include <stdint.h>

#define B_SZ 256
#define T_IN 256
#define F_IN 64
#define UE   512
#define UD   256
#define T_OUT 64
#define F_OUT 16

// ---------------------------------------------------------------------------
// Device scratch
// ---------------------------------------------------------------------------
__device__ __half g_hA_e[B_SZ * UE];            // encoder h (UNNORMALIZED, fp16)
__device__ float g_eb_p[4 * UE];                // permuted encoder bias
__device__ float g_sinv_e[B_SZ];                // final 1/S_c per batch row

__device__ __half g_UTe[2048 * 512];            // enc_rec^T fp16 (N permuted)
__device__ __half g_WTe[2048 * 64];             // enc_kernel^T fp16 (N permuted)
__device__ __half g_xA[(size_t)65536 * 64];

__device__ __half g_fKT[1024 * 512];
__device__ __half g_bKT[1024 * 512];
__device__ __half g_fUT[1024 * 256];
__device__ __half g_bUT[1024 * 256];
__device__ float g_fb_p[1024];
__device__ float g_bb_p[1024];

__device__ float g_xw_f[B_SZ * 4 * UD];
__device__ float g_xw_b[B_SZ * 4 * UD];
__device__ __half g_hAf[2 * B_SZ * UD];         // double-buffered decoder h
__device__ __half g_hAb[2 * B_SZ * UD];
__device__ float g_dec[(size_t)B_SZ * T_OUT * 2 * UD];

// cross-CTA scalar exchange
__device__ float g_partg[4 * 64 * 32];          // [mt][r][nt] softmax(g) partials
__device__ float g_partc[4 * 64 * 32];          // [mt][r][nt] sum exp(c) partials

// central-counter barriers, one 128B line each:
// enc bar1: 0..3 (mt), enc bar2: 4..7, dec: 8..15
__device__ unsigned g_bar_count[24 * 32];

__device__ __forceinline__ float sigf(float x) {
    return __fdividef(1.f, 1.f + __expf(-x));
}
__device__ __forceinline__ float ftanh(float x) {
    float e = __expf(2.f * x);
    return __fdividef(e - 1.f, e + 1.f);
}
__host__ __device__ __forceinline__ int permN(int n, int nUnits) {
    int gate = n / nUnits, u = n % nUnits;
    return ((u >> 4) << 6) | (gate << 4) | (u & 15);
}

// ---------------------------------------------------------------------------
// mma / ldmatrix helpers
// ---------------------------------------------------------------------------
__device__ __forceinline__ uint32_t smem_u32(const void* p) {
    uint32_t a;
    asm("{ .reg .u64 t; cvta.to.shared.u64 t, %1; cvt.u32.u64 %0, t; }" : "=r"(a) : "l"(p));
    return a;
}
__device__ __forceinline__ uint32_t swz(uint32_t off) { return off ^ ((off >> 3) & 0x70); }

__device__ __forceinline__ void ldsm4(uint32_t* r, uint32_t addr) {
    asm volatile("ldmatrix.sync.aligned.m8n8.x4.shared.b16 {%0,%1,%2,%3}, [%4];"
                 : "=r"(r[0]), "=r"(r[1]), "=r"(r[2]), "=r"(r[3]) : "r"(addr));
}
__device__ __forceinline__ void mma16816(float* c, const uint32_t* a, const uint32_t* b) {
    asm volatile(
        "mma.sync.aligned.m16n8k16.row.col.f32.f16.f16.f32 "
        "{%0,%1,%2,%3}, {%4,%5,%6,%7}, {%8,%9}, {%0,%1,%2,%3};"
        : "+f"(c[0]), "+f"(c[1]), "+f"(c[2]), "+f"(c[3])
        : "r"(a[0]), "r"(a[1]), "r"(a[2]), "r"(a[3]), "r"(b[0]), "r"(b[1]));
}
__device__ __forceinline__ void mma16816h(uint32_t* c, const uint32_t* a, const uint32_t* b) {
    asm volatile(
        "mma.sync.aligned.m16n8k16.row.col.f16.f16.f16.f16 "
        "{%0,%1}, {%2,%3,%4,%5}, {%6,%7}, {%0,%1};"
        : "+r"(c[0]), "+r"(c[1])
        : "r"(a[0]), "r"(a[1]), "r"(a[2]), "r"(a[3]), "r"(b[0]), "r"(b[1]));
}

// central-counter barrier, split arrive/wait (R10/R14 proven)
__device__ __forceinline__ void bar_arrive(int grp) {
    if (threadIdx.x == 0)
        asm volatile("red.release.gpu.global.add.u32 [%0], 1;"
                     :: "l"(g_bar_count + grp * 32) : "memory");
}
__device__ __forceinline__ void bar_wait_sync(int grp, unsigned target) {
    if (threadIdx.x == 0) {
        unsigned v;
        do {
            asm volatile("ld.acquire.gpu.global.u32 %0, [%1];"
                         : "=r"(v) : "l"(g_bar_count + grp * 32) : "memory");
        } while (v < target);
    }
    __syncthreads();
}

extern __shared__ __align__(16) char dynsmem[];

#define ZT_PITCH 68

// ---------------------------------------------------------------------------
// Persistent encoder — EXACT R14 structure (best measured: 1922us).
// ---------------------------------------------------------------------------
#define ENC_SMEM (18 * 8192 + 64 * ZT_PITCH * 4 + 256)

__global__ void __launch_bounds__(256, 1) enc_persistent() {
    const int tid = threadIdx.x;
    const int lane = tid & 31, wid = tid >> 5;
    const int wm = wid >> 2, wn = wid & 3;
    const int mt = blockIdx.x >> 5;
    const int nt = blockIdx.x & 31;
    const int m0 = mt * 64, n0 = nt * 64;

    char* sB = dynsmem;
    char* sA = dynsmem + 9 * 8192;
    float* zt = (float*)(dynsmem + 18 * 8192);
    float* sInv = (float*)(dynsmem + 18 * 8192 + 64 * ZT_PITCH * 4);
    const uint32_t sbase = smem_u32(dynsmem);
    const uint32_t aSb = sbase + 9 * 8192;

#pragma unroll
    for (int ck = 0; ck < 9; ++ck) {
#pragma unroll
        for (int i = 0; i < 2; ++i) {
            int idx = tid + (i << 8);
            int r = idx >> 3, c8 = (idx & 7) << 3;
            const __half* src = (ck == 0)
                ? g_WTe + (size_t)(n0 + r) * 64 + c8
                : g_UTe + (size_t)(n0 + r) * 512 + ((ck - 1) << 6) + c8;
            *(uint4*)(sB + ck * 8192 + swz((uint32_t)r * 128 + (c8 << 1))) = *(const uint4*)src;
        }
    }

    const int gr = tid >> 2;
    const int ul0 = (tid & 3) << 2;
    float cst[4] = {0.f, 0.f, 0.f, 0.f};

    const uint32_t a_row = (uint32_t)(wm * 32 + (lane & 15)) * 128 + ((lane >> 4) << 4);
    const uint32_t b_row = (uint32_t)(wn * 16 + ((lane >> 4) << 3) + (lane & 7)) * 128
                           + (((lane >> 3) & 1) << 4);

    const int sa_r = tid >> 3;
    const int sa_c8 = (tid & 7) << 3;
    const uint32_t sa_off0 = swz((uint32_t)sa_r * 128 + (sa_c8 << 1));
    const uint32_t sa_off1 = swz((uint32_t)(sa_r + 32) * 128 + (sa_c8 << 1));

    float2 bvr[2];
#pragma unroll
    for (int nf = 0; nf < 2; ++nf)
        bvr[nf] = __ldg((const float2*)(g_eb_p + n0 + wn * 16 + nf * 8 + (lane & 3) * 2));

    // stage x(0)
    {
        uint4 a0 = *(const uint4*)(g_xA + (size_t)(m0 + sa_r) * 64 + sa_c8);
        uint4 a1 = *(const uint4*)(g_xA + (size_t)(m0 + sa_r + 32) * 64 + sa_c8);
        *(uint4*)(sA + sa_off0) = a0;
        *(uint4*)(sA + sa_off1) = a1;
    }
    __syncthreads();

    for (int t = 0; t < 256; ++t) {
        float acc[2][2][4];
        uint32_t hacc[2][2][2];
#pragma unroll
        for (int a = 0; a < 2; ++a)
#pragma unroll
            for (int b = 0; b < 2; ++b) {
#pragma unroll
                for (int q = 0; q < 4; ++q) acc[a][b][q] = 0.f;
                hacc[a][b][0] = 0u; hacc[a][b][1] = 0u;
            }

        // chunk 0 (x·W), fp32 acc — overlaps other CTAs' publication
        {
#pragma unroll
            for (int k16 = 0; k16 < 4; ++k16) {
                const uint32_t kb = (uint32_t)k16 * 32;
                uint32_t af[2][4], bf[4];
                ldsm4(af[0], aSb + swz(a_row + kb));
                ldsm4(af[1], aSb + swz(a_row + 2048 + kb));
                ldsm4(bf, sbase + swz(b_row + kb));
                mma16816(acc[0][0], af[0], bf + 0);
                mma16816(acc[0][1], af[0], bf + 2);
                mma16816(acc[1][0], af[1], bf + 0);
                mma16816(acc[1][1], af[1], bf + 2);
            }
        }

        if (t > 0) {
            bar_wait_sync(4 + mt, 32u * (unsigned)t);   // h(t-1) + S_c partials ready

            const __half* h0 = g_hA_e + (size_t)(m0 + sa_r) * 512;
            const __half* h1 = g_hA_e + (size_t)(m0 + sa_r + 32) * 512;
            uint4 hv[8][2];
#pragma unroll
            for (int ck = 0; ck < 8; ++ck) {
                hv[ck][0] = __ldcg((const uint4*)(h0 + (ck << 6) + sa_c8));
                hv[ck][1] = __ldcg((const uint4*)(h1 + (ck << 6) + sa_c8));
            }
            {
                const float* pc = g_partc + (size_t)(mt * 64 + gr) * 32 + (tid & 3) * 8;
                float ps = 0.f;
#pragma unroll
                for (int j = 0; j < 8; ++j) ps += __ldcg(pc + j);
                ps += __shfl_xor_sync(0xffffffffu, ps, 1);
                ps += __shfl_xor_sync(0xffffffffu, ps, 2);
                if ((tid & 3) == 0) sInv[gr] = __fdividef(1.f, ps);
            }
#pragma unroll
            for (int ck = 0; ck < 8; ++ck) {
                char* dst = sA + (ck + 1) * 8192;
                *(uint4*)(dst + sa_off0) = hv[ck][0];
                *(uint4*)(dst + sa_off1) = hv[ck][1];
            }
            __syncthreads();

#pragma unroll
            for (int c = 1; c < 9; ++c) {
                const uint32_t aS = aSb + (uint32_t)c * 8192;
                const uint32_t bS = sbase + (uint32_t)c * 8192;
#pragma unroll
                for (int k16 = 0; k16 < 4; ++k16) {
                    const uint32_t kb = (uint32_t)k16 * 32;
                    uint32_t af[2][4], bf[4];
                    ldsm4(af[0], aS + swz(a_row + kb));
                    ldsm4(af[1], aS + swz(a_row + 2048 + kb));
                    ldsm4(bf, bS + swz(b_row + kb));
                    mma16816h(hacc[0][0], af[0], bf + 0);
                    mma16816h(hacc[0][1], af[0], bf + 2);
                    mma16816h(hacc[1][0], af[1], bf + 0);
                    mma16816h(hacc[1][1], af[1], bf + 2);
                }
            }
        }

        // epilogue -> SMEM z tile: z = xW + bias + S_inv[row] * (h_un @ U)
#pragma unroll
        for (int mf = 0; mf < 2; ++mf) {
            const int row_l = wm * 32 + mf * 16 + (lane >> 2);
#pragma unroll
            for (int nf = 0; nf < 2; ++nf) {
                const int col = wn * 16 + nf * 8 + (lane & 3) * 2;
                float2 f0 = __half22float2(*(const __half2*)&hacc[mf][nf][0]);
                float2 f1 = __half22float2(*(const __half2*)&hacc[mf][nf][1]);
                float sc0 = (t > 0) ? sInv[row_l] : 0.f;
                float sc1 = (t > 0) ? sInv[row_l + 8] : 0.f;
                zt[row_l * ZT_PITCH + col]     = acc[mf][nf][0] + bvr[nf].x + sc0 * f0.x;
                zt[row_l * ZT_PITCH + col + 1] = acc[mf][nf][1] + bvr[nf].y + sc0 * f0.y;
                zt[(row_l + 8) * ZT_PITCH + col]     = acc[mf][nf][2] + bvr[nf].x + sc1 * f1.x;
                zt[(row_l + 8) * ZT_PITCH + col + 1] = acc[mf][nf][3] + bvr[nf].y + sc1 * f1.y;
            }
        }
        __syncthreads();

        // gates phase 1: e_g = exp(zg); publish row partials
        float4 zg4 = *(float4*)(zt + gr * ZT_PITCH + 32 + ul0);
        float eg[4] = {__expf(zg4.x), __expf(zg4.y), __expf(zg4.z), __expf(zg4.w)};
        {
            float p = (eg[0] + eg[1]) + (eg[2] + eg[3]);
            p += __shfl_xor_sync(0xffffffffu, p, 1);
            p += __shfl_xor_sync(0xffffffffu, p, 2);
            if ((tid & 3) == 0) g_partg[(size_t)(mt * 64 + gr) * 32 + nt] = p;
        }
        __syncthreads();
        bar_arrive(mt);

        // stage x(t+1) in the arrive->wait gap
        if (t + 1 < 256) {
            const __half* xb = g_xA + ((size_t)(t + 1) * 256 + m0) * 64;
            uint4 a0 = *(const uint4*)(xb + (size_t)sa_r * 64 + sa_c8);
            uint4 a1 = *(const uint4*)(xb + (size_t)(sa_r + 32) * 64 + sa_c8);
            *(uint4*)(sA + sa_off0) = a0;
            *(uint4*)(sA + sa_off1) = a1;
        }

        bar_wait_sync(mt, 32u * (unsigned)(t + 1));

        // gates: S_g, then local c/h update
        {
            const float* pg = g_partg + (size_t)(mt * 64 + gr) * 32 + (tid & 3) * 8;
            float q = 0.f;
#pragma unroll
            for (int j = 0; j < 8; ++j) q += __ldcg(pg + j);
            q += __shfl_xor_sync(0xffffffffu, q, 1);
            q += __shfl_xor_sync(0xffffffffu, q, 2);
            float invsg = __fdividef(1.f, q);

            float4 zi4 = *(float4*)(zt + gr * ZT_PITCH + 0 + ul0);
            float4 zf4 = *(float4*)(zt + gr * ZT_PITCH + 16 + ul0);
            float4 zo4 = *(float4*)(zt + gr * ZT_PITCH + 48 + ul0);
            float zi[4] = {zi4.x, zi4.y, zi4.z, zi4.w};
            float zf[4] = {zf4.x, zf4.y, zf4.z, zf4.w};
            float zo[4] = {zo4.x, zo4.y, zo4.z, zo4.w};

            float hun[4], pc = 0.f;
#pragma unroll
            for (int k = 0; k < 4; ++k) {
                float cn = sigf(zf[k]) * cst[k] + sigf(zi[k]) * (eg[k] * invsg);
                cst[k] = cn;
                float ec = __expf(cn);
                pc += ec;
                hun[k] = sigf(zo[k]) * ec;
            }
            pc += __shfl_xor_sync(0xffffffffu, pc, 1);
            pc += __shfl_xor_sync(0xffffffffu, pc, 2);
            if ((tid & 3) == 0) g_partc[(size_t)(mt * 64 + gr) * 32 + nt] = pc;

            __half* hp = g_hA_e + (size_t)(m0 + gr) * 512 + 16 * nt + ul0;
            *(__half2*)hp = __floats2half2_rn(hun[0], hun[1]);
            *(__half2*)(hp + 2) = __floats2half2_rn(hun[2], hun[3]);
        }
        __syncthreads();
        bar_arrive(4 + mt);
    }
}

// tiny: reduce S_c partials into per-row 1/S (replaces 5.6us prep_encA_norm;
// the normalization itself is folded into gemm_tc's epilogue row scale)
__global__ void __launch_bounds__(256) compute_sinv() {
    const int b = threadIdx.x;            // 0..255 (one block)
    const int mt = b >> 6, r = b & 63;
    const float* pc = g_partc + (size_t)(mt * 64 + r) * 32;
    float s = 0.f;
#pragma unroll
    for (int j = 0; j < 32; ++j) s += pc[j];
    g_sinv_e[b] = __fdividef(1.f, s);
}

// ---------------------------------------------------------------------------
// Persistent decoder — EXACT R14 (R10 structure).
// ---------------------------------------------------------------------------
#define DEC_SMEM (8 * 8192 + 64 * ZT_PITCH * 4)

__global__ void __launch_bounds__(256, 1) dec_persistent() {
    const int tid = threadIdx.x;
    const int lane = tid & 31, wid = tid >> 5;
    const int wm = wid >> 2, wn = wid & 3;
    const int dir = blockIdx.x >> 6;
    const int g = (blockIdx.x >> 4) & 3;
    const int nt = blockIdx.x & 15;
    const int m0 = g * 64, n0 = nt * 64;
    const int bid = 8 + dir * 4 + g;

    const __half* Bw = dir ? g_bUT : g_fUT;
    __half* Ah = dir ? g_hAb : g_hAf;
    const float* xw = dir ? g_xw_b : g_xw_f;

    char* sB = dynsmem;
    char* sA = dynsmem + 4 * 8192;
    float* zt = (float*)(dynsmem + 8 * 8192);
    const uint32_t sbase = smem_u32(dynsmem);
    const uint32_t aSb = sbase + 4 * 8192;

    const int sa_r = tid >> 3;
    const int sa_c8 = (tid & 7) << 3;
    const uint32_t sa_off0 = swz((uint32_t)sa_r * 128 + (sa_c8 << 1));
    const uint32_t sa_off1 = swz((uint32_t)(sa_r + 32) * 128 + (sa_c8 << 1));

#pragma unroll
    for (int ck = 0; ck < 4; ++ck) {
        *(uint4*)(sB + ck * 8192 + sa_off0) =
            *(const uint4*)(Bw + (size_t)(n0 + sa_r) * 256 + (ck << 6) + sa_c8);
        *(uint4*)(sB + ck * 8192 + sa_off1) =
            *(const uint4*)(Bw + (size_t)(n0 + sa_r + 32) * 256 + (ck << 6) + sa_c8);
    }

    const int gr = tid >> 2;
    const int ul0 = (tid & 3) << 2;
    const int grow = m0 + gr;
    float cst[4] = {0.f, 0.f, 0.f, 0.f};

    const uint32_t a_row = (uint32_t)(wm * 32 + (lane & 15)) * 128 + ((lane >> 4) << 4);
    const uint32_t b_row = (uint32_t)(wn * 16 + ((lane >> 4) << 3) + (lane & 7)) * 128
                           + (((lane >> 3) & 1) << 4);

    float2 xwr[2][2][2];
#pragma unroll
    for (int mf = 0; mf < 2; ++mf) {
        const int row0 = m0 + wm * 32 + mf * 16 + (lane >> 2);
#pragma unroll
        for (int nf = 0; nf < 2; ++nf) {
            const int col = n0 + wn * 16 + nf * 8 + (lane & 3) * 2;
            xwr[mf][nf][0] = __ldg((const float2*)(xw + (size_t)row0 * 1024 + col));
            xwr[mf][nf][1] = __ldg((const float2*)(xw + (size_t)(row0 + 8) * 1024 + col));
        }
    }
    __syncthreads();

    for (int s = 0; s < 64; ++s) {
        uint32_t hacc[2][2][2];
#pragma unroll
        for (int a = 0; a < 2; ++a)
#pragma unroll
            for (int b = 0; b < 2; ++b) { hacc[a][b][0] = 0u; hacc[a][b][1] = 0u; }

        if (s > 0) {
            bar_wait_sync(bid, 16u * (unsigned)s);
            const __half* hsrc = Ah + (size_t)((s - 1) & 1) * (B_SZ * UD);
            const __half* h0 = hsrc + (size_t)(m0 + sa_r) * 256;
            const __half* h1 = hsrc + (size_t)(m0 + sa_r + 32) * 256;
            uint4 hv[4][2];
#pragma unroll
            for (int ck = 0; ck < 4; ++ck) {
                hv[ck][0] = __ldcg((const uint4*)(h0 + (ck << 6) + sa_c8));
                hv[ck][1] = __ldcg((const uint4*)(h1 + (ck << 6) + sa_c8));
            }
#pragma unroll
            for (int ck = 0; ck < 4; ++ck) {
                char* dst = sA + ck * 8192;
                *(uint4*)(dst + sa_off0) = hv[ck][0];
                *(uint4*)(dst + sa_off1) = hv[ck][1];
            }
            __syncthreads();
#pragma unroll
            for (int c = 0; c < 4; ++c) {
                const uint32_t aS = aSb + (uint32_t)c * 8192;
                const uint32_t bS = sbase + (uint32_t)c * 8192;
#pragma unroll
                for (int k16 = 0; k16 < 4; ++k16) {
                    const uint32_t kb = (uint32_t)k16 * 32;
                    uint32_t af[2][4], bf[4];
                    ldsm4(af[0], aS + swz(a_row + kb));
                    ldsm4(af[1], aS + swz(a_row + 2048 + kb));
                    ldsm4(bf, bS + swz(b_row + kb));
                    mma16816h(hacc[0][0], af[0], bf + 0);
                    mma16816h(hacc[0][1], af[0], bf + 2);
                    mma16816h(hacc[1][0], af[1], bf + 0);
                    mma16816h(hacc[1][1], af[1], bf + 2);
                }
            }
        }

#pragma unroll
        for (int mf = 0; mf < 2; ++mf) {
            const int row_l = wm * 32 + mf * 16 + (lane >> 2);
#pragma unroll
            for (int nf = 0; nf < 2; ++nf) {
                const int col = wn * 16 + nf * 8 + (lane & 3) * 2;
                float2 f0 = __half22float2(*(const __half2*)&hacc[mf][nf][0]);
                float2 f1 = __half22float2(*(const __half2*)&hacc[mf][nf][1]);
                if (s == 0) { f0.x = f0.y = f1.x = f1.y = 0.f; }
                zt[row_l * ZT_PITCH + col]     = xwr[mf][nf][0].x + f0.x;
                zt[row_l * ZT_PITCH + col + 1] = xwr[mf][nf][0].y + f0.y;
                zt[(row_l + 8) * ZT_PITCH + col]     = xwr[mf][nf][1].x + f1.x;
                zt[(row_l + 8) * ZT_PITCH + col + 1] = xwr[mf][nf][1].y + f1.y;
            }
        }
        __syncthreads();

        {
            float4 zi4 = *(float4*)(zt + gr * ZT_PITCH + 0 + ul0);
            float4 zf4 = *(float4*)(zt + gr * ZT_PITCH + 16 + ul0);
            float4 zg4 = *(float4*)(zt + gr * ZT_PITCH + 32 + ul0);
            float4 zo4 = *(float4*)(zt + gr * ZT_PITCH + 48 + ul0);
            float zi[4] = {zi4.x, zi4.y, zi4.z, zi4.w};
            float zf[4] = {zf4.x, zf4.y, zf4.z, zf4.w};
            float zg[4] = {zg4.x, zg4.y, zg4.z, zg4.w};
            float zo[4] = {zo4.x, zo4.y, zo4.z, zo4.w};

            float hn[4];
#pragma unroll
            for (int k = 0; k < 4; ++k) {
                float cn = sigf(zf[k]) * cst[k] + sigf(zi[k]) * ftanh(zg[k]);
                cst[k] = cn;
                hn[k] = sigf(zo[k]) * ftanh(cn);
            }

            __half* hp = Ah + (size_t)(s & 1) * (B_SZ * UD)
                         + (size_t)grow * 256 + 16 * nt + ul0;
            *(__half2*)hp = __floats2half2_rn(hn[0], hn[1]);
            *(__half2*)(hp + 2) = __floats2half2_rn(hn[2], hn[3]);

            int tpos = dir ? (T_OUT - 1 - s) : s;
            float* dp = g_dec + ((size_t)grow * T_OUT + tpos) * 512 + dir * 256 + 16 * nt + ul0;
            *(float4*)dp = make_float4(hn[0], hn[1], hn[2], hn[3]);
        }
        __syncthreads();
        bar_arrive(bid);
    }
}

// ---------------------------------------------------------------------------
// Generic fp16 TC GEMM with optional per-row output scale
// (decoder input projection: xw = rowscale[m]*(h_un@K) + bias)
// ---------------------------------------------------------------------------
#define STAGE_BYTES 24576
#define GEMM_SMEM (2 * STAGE_BYTES + 1024)

__global__ void __launch_bounds__(256) gemm_tc(
    const __half* __restrict__ A0, const __half* __restrict__ A1, int lda,
    const __half* __restrict__ B0, const __half* __restrict__ B1, int ldb,
    int K,
    const float* __restrict__ bias0, const float* __restrict__ bias1,
    const float* __restrict__ rowscale,
    float* __restrict__ C0, float* __restrict__ C1, int ldc)
{
    const int dir = blockIdx.z;
    const __half* A = dir ? A1 : A0;
    const __half* B = dir ? B1 : B0;
    const float* bias = dir ? bias1 : bias0;
    float* C = dir ? C1 : C0;

    const int n0 = blockIdx.x * 128;
    const int m0 = blockIdx.y * 64;
    const int tid = threadIdx.x;
    const int lane = tid & 31;
    const int wid = tid >> 5;
    const int wm = wid >> 2;
    const int wn = wid & 3;

    const uint32_t raw = smem_u32(dynsmem);
    const uint32_t sbase = (raw + 1023) & ~1023u;
    char* sb = dynsmem + (sbase - raw);

    float acc[2][4][4];
#pragma unroll
    for (int i = 0; i < 2; ++i)
#pragma unroll
        for (int j = 0; j < 4; ++j)
#pragma unroll
            for (int k = 0; k < 4; ++k) acc[i][j][k] = 0.f;

    const __half* Abase = A + (size_t)m0 * lda;
    const __half* Bbase = B + (size_t)n0 * ldb;

    uint4 rA[2], rB[4];
    const int NC = K >> 6;

#define LOAD_CHUNK(cc) do { int k0 = (cc) << 6;                                   \
    _Pragma("unroll") for (int i = 0; i < 2; ++i) {                               \
        int idx = tid + (i << 8); int r = idx >> 3; int c8 = (idx & 7) << 3;      \
        rA[i] = *(const uint4*)(Abase + (size_t)r * lda + k0 + c8); }             \
    _Pragma("unroll") for (int i = 0; i < 4; ++i) {                               \
        int idx = tid + (i << 8); int r = idx >> 3; int c8 = (idx & 7) << 3;      \
        rB[i] = *(const uint4*)(Bbase + (size_t)r * ldb + k0 + c8); } } while (0)

#define STORE_CHUNK(s) do { char* sA = sb + (s) * STAGE_BYTES; char* sB = sA + 8192; \
    _Pragma("unroll") for (int i = 0; i < 2; ++i) {                                  \
        int idx = tid + (i << 8); int r = idx >> 3; int c8 = (idx & 7) << 3;         \
        *(uint4*)(sA + swz((uint32_t)r * 128 + (c8 << 1))) = rA[i]; }                \
    _Pragma("unroll") for (int i = 0; i < 4; ++i) {                                  \
        int idx = tid + (i << 8); int r = idx >> 3; int c8 = (idx & 7) << 3;         \
        *(uint4*)(sB + swz((uint32_t)r * 128 + (c8 << 1))) = rB[i]; } } while (0)

    LOAD_CHUNK(0);
    STORE_CHUNK(0);

    for (int c = 0; c < NC; ++c) {
        __syncthreads();
        if (c + 1 < NC) LOAD_CHUNK(c + 1);

        const uint32_t aS = sbase + (c & 1) * STAGE_BYTES;
        const uint32_t bS = aS + 8192;
        const uint32_t a_row = (uint32_t)(wm * 32 + (lane & 15)) * 128 + ((lane >> 4) << 4);
        const uint32_t b_row = (uint32_t)(wn * 32 + ((lane >> 4) << 3) + (lane & 7)) * 128
                               + (((lane >> 3) & 1) << 4);
#pragma unroll
        for (int k16 = 0; k16 < 4; ++k16) {
            const uint32_t kb = (uint32_t)k16 * 32;
            uint32_t af[2][4], bf[2][4];
#pragma unroll
            for (int mf = 0; mf < 2; ++mf)
                ldsm4(af[mf], aS + swz(a_row + (uint32_t)mf * 16 * 128 + kb));
#pragma unroll
            for (int nh = 0; nh < 2; ++nh)
                ldsm4(bf[nh], bS + swz(b_row + (uint32_t)nh * 16 * 128 + kb));
#pragma unroll
            for (int mf = 0; mf < 2; ++mf)
#pragma unroll
                for (int nf = 0; nf < 4; ++nf)
                    mma16816(acc[mf][nf], af[mf], &bf[nf >> 1][(nf & 1) * 2]);
        }

        if (c + 1 < NC) STORE_CHUNK((c + 1) & 1);
    }

#pragma unroll
    for (int mf = 0; mf < 2; ++mf) {
        const int row0 = m0 + wm * 32 + mf * 16 + (lane >> 2);
        const float rs0 = rowscale ? __ldg(rowscale + row0) : 1.f;
        const float rs1 = rowscale ? __ldg(rowscale + row0 + 8) : 1.f;
#pragma unroll
        for (int nf = 0; nf < 4; ++nf) {
            const int col = n0 + wn * 32 + nf * 8 + (lane & 3) * 2;
            float2 bv = *(const float2*)(bias + col);
            *(float2*)(C + (size_t)row0 * ldc + col) =
                make_float2(rs0 * acc[mf][nf][0] + bv.x, rs0 * acc[mf][nf][1] + bv.y);
            *(float2*)(C + (size_t)(row0 + 8) * ldc + col) =
                make_float2(rs1 * acc[mf][nf][2] + bv.x, rs1 * acc[mf][nf][3] + bv.y);
        }
    }
#undef LOAD_CHUNK
#undef STORE_CHUNK
}

// ---------------------------------------------------------------------------
// Prep kernels (consolidated)
// ---------------------------------------------------------------------------
__global__ void __launch_bounds__(256) prep_all(
    const float* __restrict__ x, const float* __restrict__ eb,
    const float* __restrict__ fb, const float* __restrict__ bb)
{
    const int total = 65536 * 64;
    int gi = blockIdx.x * blockDim.x + threadIdx.x;
    if (gi < 24 * 32) g_bar_count[gi] = 0u;
    if (gi < 2048) g_eb_p[permN(gi, 512)] = eb[gi];
    if (gi >= 2048 && gi < 3072) {
        int n = gi - 2048;
        int np = permN(n, 256);
        g_fb_p[np] = fb[n];
        g_bb_p[np] = bb[n];
    }
    for (int i = gi; i < total; i += gridDim.x * blockDim.x) {
        int r = i >> 6, c = i & 63;
        int t = r >> 8, b = r & 255;
        g_xA[(size_t)r * 64 + c] = __float2half_rn(x[((size_t)b * T_IN + t) * F_IN + c]);
    }
}

// One launch for all 6 weight transposes. blockIdx.z selects the matrix.
__global__ void __launch_bounds__(256) transpose_all(
    const float* __restrict__ eU, const float* __restrict__ eW,
    const float* __restrict__ fK, const float* __restrict__ bK,
    const float* __restrict__ fU, const float* __restrict__ bU,
    __half* __restrict__ UTe, __half* __restrict__ WTe,
    __half* __restrict__ fKT, __half* __restrict__ bKT,
    __half* __restrict__ fUT, __half* __restrict__ bUT)
{
    const float* in; __half* out;
    int K, N, nUnits;
    switch (blockIdx.z) {
        case 0: in = eU; out = UTe; K = 512; N = 2048; nUnits = 512; break;
        case 1: in = eW; out = WTe; K = 64;  N = 2048; nUnits = 512; break;
        case 2: in = fK; out = fKT; K = 512; N = 1024; nUnits = 256; break;
        case 3: in = bK; out = bKT; K = 512; N = 1024; nUnits = 256; break;
        case 4: in = fU; out = fUT; K = 256; N = 1024; nUnits = 256; break;
        default: in = bU; out = bUT; K = 256; N = 1024; nUnits = 256; break;
    }
    const int nb = blockIdx.x * 32;
    const int kb = blockIdx.y * 32;
    if (nb >= N || kb >= K) return;

    __shared__ float tile[32][33];
    const int tx = threadIdx.x & 31;
    const int ty = threadIdx.x >> 5;
#pragma unroll
    for (int i = ty; i < 32; i += 8)
        tile[i][tx] = in[(size_t)(kb + i) * N + nb + tx];
    __syncthreads();
#pragma unroll
    for (int i = ty; i < 32; i += 8) {
        int n = nb + i;
        int np = permN(n, nUnits);
        out[(size_t)np * K + kb + tx] = __float2half_rn(tile[tx][i]);
    }
}

__global__ void __launch_bounds__(256) dense_kernel_(
    const float* __restrict__ Wd, const float* __restrict__ bd, float* __restrict__ out)
{
    __shared__ float sdec[16][512];
    const int row0 = blockIdx.x * 16;
#pragma unroll
    for (int i = 0; i < 8; ++i) {
        int f = threadIdx.x + i * 256;
        int r = f >> 7;
        int k4 = (f & 127) * 4;
        *reinterpret_cast<float4*>(&sdec[r][k4]) =
            *reinterpret_cast<const float4*>(g_dec + (size_t)(row0 + r) * 512 + k4);
    }
    __syncthreads();
    const int r = threadIdx.x >> 4;
    const int m = threadIdx.x & 15;
    float acc = 0.f;
#pragma unroll 8
    for (int k = 0; k < 512; ++k)
        acc += sdec[r][k] * __ldg(Wd + k * 16 + m);
    out[(size_t)(row0 + r) * 16 + m] = acc + bd[m];
}

// ---------------------------------------------------------------------------
// Launch — 7 launches total
// ---------------------------------------------------------------------------
extern "C" void kernel_launch(void* const* d_in, const int* in_sizes, int n_in,
                              void* d_out, int out_size) {
    const float* x   = (const float*)d_in[0];
    const float* eW  = (const float*)d_in[1];
    const float* eU  = (const float*)d_in[2];
    const float* eb  = (const float*)d_in[3];
    const float* fK  = (const float*)d_in[4];
    const float* fU  = (const float*)d_in[5];
    const float* fb  = (const float*)d_in[6];
    const float* bK  = (const float*)d_in[7];
    const float* bU  = (const float*)d_in[8];
    const float* bb  = (const float*)d_in[9];
    const float* dW  = (const float*)d_in[10];
    const float* db  = (const float*)d_in[11];
    float* out = (float*)d_out;

    cudaFuncSetAttribute(gemm_tc, cudaFuncAttributeMaxDynamicSharedMemorySize, GEMM_SMEM);
    cudaFuncSetAttribute(enc_persistent, cudaFuncAttributeMaxDynamicSharedMemorySize, ENC_SMEM);
    cudaFuncSetAttribute(dec_persistent, cudaFuncAttributeMaxDynamicSharedMemorySize, DEC_SMEM);

    float *xwf_p, *xwb_p, *fbp_p, *bbp_p, *sinv_p;
    __half *UTe_p, *WTe_p, *hAe_p, *fKT_p, *bKT_p, *fUT_p, *bUT_p;
    cudaGetSymbolAddress((void**)&xwf_p, g_xw_f);
    cudaGetSymbolAddress((void**)&xwb_p, g_xw_b);
    cudaGetSymbolAddress((void**)&fbp_p, g_fb_p);
    cudaGetSymbolAddress((void**)&bbp_p, g_bb_p);
    cudaGetSymbolAddress((void**)&sinv_p, g_sinv_e);
    cudaGetSymbolAddress((void**)&UTe_p, g_UTe);
    cudaGetSymbolAddress((void**)&WTe_p, g_WTe);
    cudaGetSymbolAddress((void**)&hAe_p, g_hA_e);
    cudaGetSymbolAddress((void**)&fKT_p, g_fKT);
    cudaGetSymbolAddress((void**)&bKT_p, g_bKT);
    cudaGetSymbolAddress((void**)&fUT_p, g_fUT);
    cudaGetSymbolAddress((void**)&bUT_p, g_bUT);

    prep_all<<<1024, 256>>>(x, eb, fb, bb);
    transpose_all<<<dim3(64, 16, 6), 256>>>(eU, eW, fK, bK, fU, bU,
                                            UTe_p, WTe_p, fKT_p, bKT_p, fUT_p, bUT_p);

    enc_persistent<<<128, 256, ENC_SMEM>>>();

    compute_sinv<<<1, 256>>>();
    // xw = sinv[m] * (h_un @ K^T) + bias   (normalization folded into epilogue)
    gemm_tc<<<dim3(8, 4, 2), 256, GEMM_SMEM>>>(
        hAe_p, hAe_p, 512, fKT_p, bKT_p, 512, 512,
        fbp_p, bbp_p, sinv_p, xwf_p, xwb_p, 1024);

    dec_persistent<<<128, 256, DEC_SMEM>>>();

    dense_kernel_<<<(B_SZ * T_OUT) / 16, 256>>>(dW, db, out);
}